// round 16
// baseline (speedup 1.0000x reference)
// SAGNetworkHierarchical GB300 kernel, round 16.
// R15 regressed (unconditional loads + unroll pressure): conv reverted to
// R14 form. k_alloc folded into k_front's degree-role last-block tail
// (one fewer launch; conv b0 now lands in the profiled ncu slot).
#include <cuda_runtime.h>
#include <cuda_fp16.h>
#include <mma.h>
#include <math.h>
using namespace nvcuda;

#define NN 50000
#define EE 800000
#define HB 65536
#define TCAP 2048
#define EGRID 3125   // ceil(EE/256)

__device__ __half    g_hs[NN * 128];
__device__ __half    g_hrelu[NN * 128];
__device__ __half    g_Wh[3 * 128 * 128];
__device__ float     g_hs2[NN];
__device__ float     g_score[NN];
__device__ unsigned  g_key[NN];
__device__ int       g_deg_in[NN];
__device__ int       g_deg_out[NN];
__device__ int       g_deg0[NN];
__device__ int       g_rowptr[NN];
__device__ int       g_csr[EE];
__device__ int       g_ord[EE];
__device__ int       g_alive[NN];
__device__ int       g_list[2][NN];
__device__ float     g_mean[128];
__device__ float     g_bmax[3 * 128];
__device__ int       g_hist[HB];
__device__ int       g_bucketHi;
__device__ int       g_cntAbove;
__device__ int       g_selcnt;
__device__ int       g_candcnt;
__device__ int       g_done;
__device__ unsigned  g_candk[NN];
__device__ int       g_candv[NN];

__device__ __forceinline__ unsigned okey(float f) {
    unsigned u = __float_as_uint(f);
    return (u & 0x80000000u) ? ~u : (u | 0x80000000u);
}
__device__ __forceinline__ void atomicMaxF(float* a, float v) {
    if (v >= 0.f) atomicMax((int*)a, __float_as_int(v));
    else          atomicMin((unsigned*)a, __float_as_uint(v));
}
__device__ __forceinline__ float invs(int d) {
    return 1.0f / sqrtf((float)(d > 0 ? d : 1));
}

__global__ void k_init0(const float* __restrict__ W0, const float* __restrict__ W1,
                        const float* __restrict__ W2) {
    int i = blockIdx.x * blockDim.x + threadIdx.x;
    if (i < NN) { g_alive[i] = 1; g_list[0][i] = i; g_deg_in[i] = 0; g_deg_out[i] = 0; }
    if (i < HB) g_hist[i] = 0;
    if (i < 128) g_mean[i] = 0.f;
    if (i < 3 * 128) g_bmax[i] = __int_as_float(0xff800000);
    if (i < 128 * 128) {
        g_Wh[i]         = __float2half(W0[i]);
        g_Wh[16384 + i] = __float2half(W1[i]);
        g_Wh[32768 + i] = __float2half(W2[i]);
    }
    if (i == 0) { g_selcnt = 0; g_candcnt = 0; g_done = 0; }
}
// front(b): gemm role (HMMA) | degree role (+b0 rowptr-scan tail) | pool(b-1).
__global__ __launch_bounds__(256, 4) void k_front(
    const float* __restrict__ x,
    int lin, int nA, int useTh,
    const int* __restrict__ src, const int* __restrict__ dst, int mode,
    int gemmG, int poolBm, float invk) {
    __shared__ __align__(16) char gsm[64 * 128 * 4];
    __shared__ int rid[64];
    __shared__ float sth[64];
    __half* XSH = (__half*)gsm;
    float*  OUT = (float*)gsm;
    int tid = threadIdx.x;
    if (blockIdx.x >= gemmG + EGRID) {
        // ---- pool role for previous block ----
        int pb = blockIdx.x - gemmG - EGRID;
        int base = pb * 64;
        int lim = min(64, nA - base);
        if (tid < 64 && tid < lim) {
            int v = g_list[lin][base + tid];
            rid[tid] = v;
            sth[tid] = tanhf(g_score[v]);
        }
        __syncthreads();
        int c = tid & 127, half = tid >> 7;
        int j0 = half * 32, j1 = min(lim, j0 + 32);
        float msum = 0.f, mmax = __int_as_float(0xff800000);
        for (int j = j0; j < j1; j++) {
            float val = __half2float(g_hrelu[rid[j] * 128 + c]) * sth[j];
            msum += val;
            mmax = fmaxf(mmax, val);
        }
        if (j0 < lim) {
            atomicAdd(&g_mean[c], msum * invk);
            atomicMaxF(&g_bmax[poolBm * 128 + c], mmax);
        }
        return;
    }
    if (blockIdx.x >= gemmG) {
        // ---- degree role ----
        int i = (blockIdx.x - gemmG) * 256 + tid;
        if (mode == 0) {
            if (i < EE) {
                atomicAdd(&g_deg_out[src[i]], 1);
                g_ord[i] = atomicAdd(&g_deg_in[dst[i]], 1);
            }
            // last degree block: rowptr exclusive scan + deg0 freeze
            __shared__ bool isLast;
            __shared__ int ps[256];
            __threadfence();
            __syncthreads();
            if (tid == 0) isLast = (atomicAdd(&g_done, 1) == EGRID - 1);
            __syncthreads();
            if (!isLast) return;
            if (tid == 0) g_done = 0;
            const int CH = (NN + 255) / 256;   // 196
            int lo = tid * CH, hi = min(NN, lo + CH);
            int s = 0;
            for (int q = lo; q < hi; q++) s += g_deg_in[q];
            ps[tid] = s;
            __syncthreads();
            for (int off = 1; off < 256; off <<= 1) {
                int t2 = (tid >= off) ? ps[tid - off] : 0;
                __syncthreads();
                ps[tid] += t2;
                __syncthreads();
            }
            int pre = (tid > 0) ? ps[tid - 1] : 0;
            for (int q = lo; q < hi; q++) {
                int d = g_deg_in[q];
                g_rowptr[q] = pre;
                g_deg0[q] = d;
                pre += d;
            }
            return;
        }
        if (i < EE) {
            int s = src[i], d = dst[i];
            if (g_alive[s] && g_alive[d]) {
                atomicAdd(&g_deg_out[s], 1);
                atomicAdd(&g_deg_in[d], 1);
            }
        }
        return;
    }
    // ---- gemm role (HMMA) ----
    if (tid < 64) {
        int r = blockIdx.x * 64 + tid;
        int v = (r < nA) ? g_list[lin][r] : -1;
        rid[tid] = v;
        sth[tid] = (v >= 0) ? (useTh ? tanhf(g_score[v]) : 1.0f) : 0.f;
    }
    __syncthreads();
    for (int i = tid; i < 2048; i += 256) {
        int row = i >> 5, c4 = (i & 31) * 4;
        int v = rid[row];
        __half2 h01, h23;
        if (v >= 0) {
            if (x) {
                float4 xv = *(const float4*)&x[v * 128 + c4];
                h01 = __floats2half2_rn(xv.x, xv.y);
                h23 = __floats2half2_rn(xv.z, xv.w);
            } else {
                uint2 p = *(const uint2*)&g_hrelu[v * 128 + c4];
                h01 = *(__half2*)&p.x;
                h23 = *(__half2*)&p.y;
            }
        } else {
            h01 = __floats2half2_rn(0.f, 0.f);
            h23 = h01;
        }
        *(__half2*)&XSH[row * 136 + c4] = h01;
        *(__half2*)&XSH[row * 136 + c4 + 2] = h23;
    }
    __syncthreads();
    int w = tid >> 5;
    int rr = (w & 3) * 16, ch = (w >> 2) * 64;
    wmma::fragment<wmma::matrix_a, 16, 16, 16, __half, wmma::row_major> fa;
    wmma::fragment<wmma::matrix_b, 16, 16, 16, __half, wmma::row_major> fb;
    wmma::fragment<wmma::accumulator, 16, 16, 16, float> fc[4];
#pragma unroll
    for (int f = 0; f < 4; f++) wmma::fill_fragment(fc[f], 0.f);
    const __half* Wh = g_Wh + mode * 16384;
#pragma unroll
    for (int k0 = 0; k0 < 128; k0 += 16) {
        wmma::load_matrix_sync(fa, XSH + rr * 136 + k0, 136);
#pragma unroll
        for (int f = 0; f < 4; f++) {
            wmma::load_matrix_sync(fb, Wh + k0 * 128 + ch + f * 16, 128);
            wmma::mma_sync(fc[f], fa, fb, fc[f]);
        }
    }
    __syncthreads();
#pragma unroll
    for (int f = 0; f < 4; f++)
        wmma::store_matrix_sync(OUT + rr * 128 + ch + f * 16, fc[f], 128, wmma::mem_row_major);
    __syncthreads();
    for (int i = tid; i < 2048; i += 256) {
        int row = i >> 5, c4 = (i & 31) * 4;
        int v = rid[row];
        if (v >= 0) {
            float s = sth[row];
            float4 o = *(float4*)&OUT[row * 128 + c4];
            __half2 h01 = __floats2half2_rn(o.x * s, o.y * s);
            __half2 h23 = __floats2half2_rn(o.z * s, o.w * s);
            uint2 st;
            st.x = *(unsigned*)&h01; st.y = *(unsigned*)&h23;
            *(uint2*)&g_hs[v * 128 + c4] = st;
        }
    }
}
__global__ void k_scatter(const int* __restrict__ src, const int* __restrict__ dst) {
    int i = blockIdx.x * blockDim.x + threadIdx.x;
    if (i >= EE) return;
    g_csr[g_rowptr[dst[i]] + g_ord[i]] = src[i];
}
// gather-SpMM (R14 form); dead u flagged deg_out = -1 -> skipped
__global__ __launch_bounds__(256) void k_spmm_conv(const float* __restrict__ cb,
                                                   const float* __restrict__ sW,
                                                   int lin, int nA) {
    int gw = (blockIdx.x * blockDim.x + threadIdx.x) >> 5;
    int lane = threadIdx.x & 31;
    if (gw >= nA) return;
    int v = g_list[lin][gw];
    int s = g_rowptr[v];
    int nb = g_deg0[v];
    float a0 = 0.f, a1 = 0.f, a2 = 0.f, a3 = 0.f;
    for (int i0 = 0; i0 < nb; i0 += 32) {
        int u32 = 0; float ns32 = 0.f;
        if (i0 + lane < nb) {
            u32 = g_csr[s + i0 + lane];
            int du = g_deg_out[u32];
            ns32 = (du < 0) ? 0.f : invs(du);
        }
        int lim = min(32, nb - i0);
        for (int j = 0; j < lim; j++) {
            float nsu = __shfl_sync(~0u, ns32, j);
            int u = __shfl_sync(~0u, u32, j);
            if (nsu != 0.f) {
                uint2 p = *(const uint2*)&g_hs[u * 128 + lane * 4];
                float2 f01 = __half22float2(*(__half2*)&p.x);
                float2 f23 = __half22float2(*(__half2*)&p.y);
                a0 = fmaf(f01.x, nsu, a0); a1 = fmaf(f01.y, nsu, a1);
                a2 = fmaf(f23.x, nsu, a2); a3 = fmaf(f23.y, nsu, a3);
            }
        }
    }
    float ndv = invs(g_deg_in[v]);
    float4 b = *(const float4*)&cb[lane * 4];
    float4 hr;
    hr.x = fmaxf(fmaf(a0, ndv, b.x), 0.f);
    hr.y = fmaxf(fmaf(a1, ndv, b.y), 0.f);
    hr.z = fmaxf(fmaf(a2, ndv, b.z), 0.f);
    hr.w = fmaxf(fmaf(a3, ndv, b.w), 0.f);
    __half2 h01 = __floats2half2_rn(hr.x, hr.y);
    __half2 h23 = __floats2half2_rn(hr.z, hr.w);
    uint2 o;
    o.x = *(unsigned*)&h01; o.y = *(unsigned*)&h23;
    *(uint2*)&g_hrelu[v * 128 + lane * 4] = o;
    float4 w = *(const float4*)&sW[lane * 4];
    float sd = hr.x * w.x + hr.y * w.y + hr.z * w.z + hr.w * w.w;
#pragma unroll
    for (int oo = 16; oo; oo >>= 1) sd += __shfl_down_sync(~0u, sd, oo);
    if (lane == 0) g_hs2[v] = sd * invs(g_deg_out[v]);
}
// score + key + hist; LAST block picks the k-th-largest 16-bit bucket
__global__ __launch_bounds__(256) void k_spmm_score(const float* __restrict__ sb,
                                                    int lin, int nA, int k) {
    __shared__ bool isLast;
    __shared__ int A[256];
    int tid = threadIdx.x;
    int gw = (blockIdx.x * 256 + tid) >> 5;
    int lane = tid & 31;
    if (gw < nA) {
        int v = g_list[lin][gw];
        int s = g_rowptr[v], e = s + g_deg0[v];
        float sum = 0.f;
        for (int i = s + lane; i < e; i += 32) sum += g_hs2[g_csr[i]];
#pragma unroll
        for (int o = 16; o; o >>= 1) sum += __shfl_down_sync(~0u, sum, o);
        if (lane == 0) {
            float sc = fmaf(sum, invs(g_deg_in[v]), sb[0]);
            g_score[v] = sc;
            unsigned kk = okey(sc);
            g_key[v] = kk;
            atomicAdd(&g_hist[kk >> 16], 1);
        }
    }
    __threadfence();
    __syncthreads();
    if (tid == 0) isLast = (atomicAdd(&g_done, 1) == gridDim.x - 1);
    __syncthreads();
    if (!isLast) return;
    if (tid == 0) g_done = 0;
    const int4* h4 = (const int4*)g_hist;
    int base4 = tid * 64;
    int s = 0;
#pragma unroll 8
    for (int b = 0; b < 64; b++) { int4 v = h4[base4 + b]; s += v.x + v.y + v.z + v.w; }
    A[tid] = s;
    __syncthreads();
    for (int off = 1; off < 256; off <<= 1) {
        int w = A[tid] + ((tid + off < 256) ? A[tid + off] : 0);
        __syncthreads();
        A[tid] = w;
        __syncthreads();
    }
    int above = A[tid] - s;
    if (above < k && above + s >= k) {
        int cum = above;
        int base = tid * 256;
        for (int b = 255; b >= 0; b--) {
            int h = g_hist[base + b];
            if (cum + h >= k) { g_bucketHi = base + b; g_cntAbove = cum; break; }
            cum += h;
        }
    }
}
// split + kill + hist zero; LAST block refines low 16 bits
__global__ __launch_bounds__(256) void k_cand(int lin, int lout, int nA, int k) {
    __shared__ bool isLast;
    __shared__ int hist[256];
    __shared__ int sh_b1, sh_rem1, sh_b0, sh_needed, sh_tc;
    __shared__ int tiebuf[TCAP];
    int tid = threadIdx.x;
    int gid = blockIdx.x * 256 + tid;
    for (int j = gid; j < HB; j += gridDim.x * 256) g_hist[j] = 0;
    int bh = g_bucketHi;
    int v = -1; unsigned key = 0; int hi = -1;
    if (gid < nA) { v = g_list[lin][gid]; key = g_key[v]; hi = (int)(key >> 16); }
    bool gt = (gid < nA) && (hi > bh);
    bool eq = (gid < nA) && (hi == bh);
    int lane = tid & 31;
    unsigned m = __ballot_sync(~0u, gt);
    if (m) {
        int ldr = __ffs(m) - 1; int base;
        if (lane == ldr) base = atomicAdd(&g_selcnt, __popc(m));
        base = __shfl_sync(~0u, base, ldr);
        if (gt) {
            g_list[lout][base + __popc(m & ((1u << lane) - 1))] = v;
            g_deg_in[v] = 0; g_deg_out[v] = 0;
        }
    }
    unsigned m2 = __ballot_sync(~0u, eq);
    if (m2) {
        int ldr = __ffs(m2) - 1; int base;
        if (lane == ldr) base = atomicAdd(&g_candcnt, __popc(m2));
        base = __shfl_sync(~0u, base, ldr);
        if (eq) {
            int p = base + __popc(m2 & ((1u << lane) - 1));
            g_candk[p] = key; g_candv[p] = v;
        }
    }
    if (gid < nA && !gt && !eq) { g_alive[v] = 0; g_deg_out[v] = -1; g_hs2[v] = 0.f; }
    __threadfence();
    __syncthreads();
    if (tid == 0) isLast = (atomicAdd(&g_done, 1) == gridDim.x - 1);
    __syncthreads();
    if (!isLast) return;
    if (tid == 0) g_done = 0;
    int C = g_candcnt;
    int kp = k - g_cntAbove;
    hist[tid] = 0;
    if (tid == 0) sh_tc = 0;
    __syncthreads();
    for (int i = tid; i < C; i += 256) atomicAdd(&hist[(g_candk[i] >> 8) & 255], 1);
    __syncthreads();
    if (tid == 0) {
        int cum = 0;
        for (int b = 255; b >= 0; b--) {
            int h = hist[b];
            if (cum + h >= kp) { sh_b1 = b; sh_rem1 = kp - cum; break; }
            cum += h;
        }
    }
    __syncthreads();
    int b1 = sh_b1, rem1 = sh_rem1;
    hist[tid] = 0;
    __syncthreads();
    for (int i = tid; i < C; i += 256) {
        unsigned kk = g_candk[i];
        if ((int)((kk >> 8) & 255) == b1) atomicAdd(&hist[kk & 255], 1);
    }
    __syncthreads();
    if (tid == 0) {
        int cum = 0;
        for (int b = 255; b >= 0; b--) {
            int h = hist[b];
            if (cum + h >= rem1) { sh_b0 = b; sh_needed = rem1 - cum; break; }
            cum += h;
        }
    }
    __syncthreads();
    unsigned lo_t = ((unsigned)b1 << 8) | (unsigned)sh_b0;
    int needed = sh_needed;
    for (int i = tid; i < C; i += 256) {
        unsigned lo = g_candk[i] & 0xFFFFu;
        int vv = g_candv[i];
        if (lo > lo_t) {
            int p = atomicAdd(&g_selcnt, 1);
            g_list[lout][p] = vv;
            g_deg_in[vv] = 0; g_deg_out[vv] = 0;
        } else if (lo < lo_t) {
            g_alive[vv] = 0; g_deg_out[vv] = -1; g_hs2[vv] = 0.f;
        } else {
            int p = atomicAdd(&sh_tc, 1);
            if (p < TCAP) tiebuf[p] = vv;
        }
    }
    __syncthreads();
    int T = sh_tc;
    if (T <= needed) {
        for (int i = tid; i < C; i += 256) {
            if ((g_candk[i] & 0xFFFFu) == lo_t) {
                int vv = g_candv[i];
                int p = atomicAdd(&g_selcnt, 1);
                g_list[lout][p] = vv;
                g_deg_in[vv] = 0; g_deg_out[vv] = 0;
            }
        }
    } else if (T <= TCAP) {
        for (int j = tid; j < T; j += 256) {
            int vj = tiebuf[j];
            int r = 0;
            for (int q = 0; q < T; q++) r += (tiebuf[q] < vj);
            if (r < needed) {
                int p = atomicAdd(&g_selcnt, 1);
                g_list[lout][p] = vj;
                g_deg_in[vj] = 0; g_deg_out[vj] = 0;
            } else { g_alive[vj] = 0; g_deg_out[vj] = -1; g_hs2[vj] = 0.f; }
        }
    } else {
        for (int i = tid; i < C; i += 256) {
            if ((g_candk[i] & 0xFFFFu) != lo_t) continue;
            int vi = g_candv[i];
            int r = 0;
            for (int q = 0; q < C; q++)
                if ((g_candk[q] & 0xFFFFu) == lo_t && g_candv[q] < vi) r++;
            if (r < needed) {
                int p = atomicAdd(&g_selcnt, 1);
                g_list[lout][p] = vi;
                g_deg_in[vi] = 0; g_deg_out[vi] = 0;
            } else { g_alive[vi] = 0; g_deg_out[vi] = -1; g_hs2[vi] = 0.f; }
        }
    }
    __syncthreads();
    if (tid == 0) { g_selcnt = 0; g_candcnt = 0; }
}
__global__ __launch_bounds__(128) void k_pool(int bm, int lst, int kb, float invk) {
    __shared__ float sth[64];
    __shared__ int sv[64];
    int c = threadIdx.x;
    int base = blockIdx.x * 64;
    int lim = min(64, kb - base);
    if (c < 64 && c < lim) {
        int v = g_list[lst][base + c];
        sv[c] = v;
        sth[c] = tanhf(g_score[v]);
    }
    __syncthreads();
    float msum = 0.f, mmax = __int_as_float(0xff800000);
    for (int j = 0; j < lim; j++) {
        float val = __half2float(g_hrelu[sv[j] * 128 + c]) * sth[j];
        msum += val;
        mmax = fmaxf(mmax, val);
    }
    atomicAdd(&g_mean[c], msum * invk);
    atomicMaxF(&g_bmax[bm * 128 + c], mmax);
}
__global__ __launch_bounds__(1024) void k_mlp(const float* __restrict__ seq,
                                              const float* __restrict__ W1, const float* __restrict__ b1,
                                              const float* __restrict__ W2, const float* __restrict__ b2,
                                              const float* __restrict__ W3, const float* __restrict__ b3,
                                              float* __restrict__ out) {
    __shared__ float fin[1280];
    __shared__ float red[1024];
    __shared__ float f1[256];
    __shared__ float f2[128];
    int t = threadIdx.x;
    for (int i = t; i < 1280; i += 1024) {
        float v;
        if (i < 128)      v = g_mean[i];
        else if (i < 256) v = g_bmax[i - 128] + g_bmax[128 + (i - 128)] + g_bmax[256 + (i - 128)];
        else              v = seq[i - 256];
        fin[i] = v;
    }
    __syncthreads();
    {
        int o = t & 255, part = t >> 8;
        float acc = 0.f;
        int k0 = part * 320;
        for (int k = k0; k < k0 + 320; k++) acc = fmaf(fin[k], W1[k * 256 + o], acc);
        red[t] = acc;
    }
    __syncthreads();
    if (t < 256) {
        float s = red[t] + red[t + 256] + red[t + 512] + red[t + 768] + b1[t];
        f1[t] = fmaxf(s, 0.f);
    }
    __syncthreads();
    if (t < 128) {
        float acc = b2[t];
        for (int k = 0; k < 256; k++) acc = fmaf(f1[k], W2[k * 128 + t], acc);
        f2[t] = fmaxf(acc, 0.f);
    }
    __syncthreads();
#pragma unroll
    for (int r = 0; r < 2; r++) {
        int o = t + r * 1024;
        float acc = b3[o];
        for (int k = 0; k < 128; k++) acc = fmaf(f2[k], W3[k * 2048 + o], acc);
        out[o] = acc;
    }
}

extern "C" void kernel_launch(void* const* d_in, const int* in_sizes, int n_in,
                              void* d_out, int out_size) {
    const float* feat = (const float*)d_in[0];
    const float* seq  = (const float*)d_in[1];
    const int*   src  = (const int*)d_in[2];
    const int*   dst  = (const int*)d_in[3];
    const float* cW[3] = {(const float*)d_in[6],  (const float*)d_in[10], (const float*)d_in[14]};
    const float* cb[3] = {(const float*)d_in[7],  (const float*)d_in[11], (const float*)d_in[15]};
    const float* sW[3] = {(const float*)d_in[8],  (const float*)d_in[12], (const float*)d_in[16]};
    const float* sb[3] = {(const float*)d_in[9],  (const float*)d_in[13], (const float*)d_in[17]};
    const float* l1W = (const float*)d_in[18];
    const float* l1b = (const float*)d_in[19];
    const float* l2W = (const float*)d_in[20];
    const float* l2b = (const float*)d_in[21];
    const float* l3W = (const float*)d_in[22];
    const float* l3b = (const float*)d_in[23];
    float* out = (float*)d_out;

    const int nAv[3] = {50000, 25000, 12500};
    const int kbv[3] = {25000, 12500, 6250};

    k_init0<<<(HB + 255) / 256, 256>>>(cW[0], cW[1], cW[2]);
    for (int b = 0; b < 3; b++) {
        int nA = nAv[b], kb = kbv[b];
        int lin = b & 1, lout = 1 - lin;
        int gemmG = (nA + 63) / 64;
        int poolG = (b > 0) ? gemmG : 0;
        k_front<<<gemmG + EGRID + poolG, 256>>>(
            b == 0 ? feat : (const float*)0, lin, nA, b > 0,
            src, dst, b, gemmG, b - 1, 1.0f / (float)nA);
        if (b == 0) k_scatter<<<EGRID, 256>>>(src, dst);
        k_spmm_conv<<<(nA + 7) / 8, 256>>>(cb[b], sW[b], lin, nA);
        k_spmm_score<<<(nA + 7) / 8, 256>>>(sb[b], lin, nA, kb);
        k_cand<<<(nA + 255) / 256, 256>>>(lin, lout, nA, kb);
    }
    k_pool<<<(6250 + 63) / 64, 128>>>(2, 1, 6250, 1.0f / 6250.0f);
    k_mlp<<<1, 1024>>>(seq, l1W, l1b, l2W, l2b, l3W, l3b, out);
}

// round 17
// speedup vs baseline: 1.2903x; 1.2903x over previous
// SAGNetworkHierarchical GB300 kernel, round 17.
// R16: alloc-fold serialized a 50k scan into one block (-90us) -> reverted;
// its probe showed conv is ISSUE-bound (55% issue, fma 24 / alu 24, L2 22).
// This round: R14 config restored + conv accumulates in half2 via HFMA2
// (deletes 4 cvt + 4 FFMA per edge; fp32 conversion once per node).
#include <cuda_runtime.h>
#include <cuda_fp16.h>
#include <mma.h>
#include <math.h>
using namespace nvcuda;

#define NN 50000
#define EE 800000
#define HB 65536
#define TCAP 2048
#define EGRID 3125   // ceil(EE/256)

__device__ __half    g_hs[NN * 128];
__device__ __half    g_hrelu[NN * 128];
__device__ __half    g_Wh[3 * 128 * 128];
__device__ float     g_hs2[NN];
__device__ float     g_score[NN];
__device__ unsigned  g_key[NN];
__device__ int       g_deg_in[NN];
__device__ int       g_deg_out[NN];
__device__ int       g_deg0[NN];
__device__ int       g_rowptr[NN];
__device__ int       g_csr[EE];
__device__ int       g_ord[EE];
__device__ int       g_alive[NN];
__device__ int       g_list[2][NN];
__device__ float     g_mean[128];
__device__ float     g_bmax[3 * 128];
__device__ int       g_total;
__device__ int       g_hist[HB];
__device__ int       g_bucketHi;
__device__ int       g_cntAbove;
__device__ int       g_selcnt;
__device__ int       g_candcnt;
__device__ int       g_done;
__device__ unsigned  g_candk[NN];
__device__ int       g_candv[NN];

__device__ __forceinline__ unsigned okey(float f) {
    unsigned u = __float_as_uint(f);
    return (u & 0x80000000u) ? ~u : (u | 0x80000000u);
}
__device__ __forceinline__ void atomicMaxF(float* a, float v) {
    if (v >= 0.f) atomicMax((int*)a, __float_as_int(v));
    else          atomicMin((unsigned*)a, __float_as_uint(v));
}
__device__ __forceinline__ float invs(int d) {
    return 1.0f / sqrtf((float)(d > 0 ? d : 1));
}

__global__ void k_init0(const float* __restrict__ W0, const float* __restrict__ W1,
                        const float* __restrict__ W2) {
    int i = blockIdx.x * blockDim.x + threadIdx.x;
    if (i < NN) { g_alive[i] = 1; g_list[0][i] = i; g_deg_in[i] = 0; g_deg_out[i] = 0; }
    if (i < HB) g_hist[i] = 0;
    if (i < 128) g_mean[i] = 0.f;
    if (i < 3 * 128) g_bmax[i] = __int_as_float(0xff800000);
    if (i < 128 * 128) {
        g_Wh[i]         = __float2half(W0[i]);
        g_Wh[16384 + i] = __float2half(W1[i]);
        g_Wh[32768 + i] = __float2half(W2[i]);
    }
    if (i == 0) { g_total = 0; g_selcnt = 0; g_candcnt = 0; g_done = 0; }
}
// front(b): gemm role (HMMA) | degree role | pool(b-1) role.
__global__ __launch_bounds__(256, 4) void k_front(
    const float* __restrict__ x,
    int lin, int nA, int useTh,
    const int* __restrict__ src, const int* __restrict__ dst, int mode,
    int gemmG, int poolBm, float invk) {
    __shared__ __align__(16) char gsm[64 * 128 * 4];
    __shared__ int rid[64];
    __shared__ float sth[64];
    __half* XSH = (__half*)gsm;
    float*  OUT = (float*)gsm;
    int tid = threadIdx.x;
    if (blockIdx.x >= gemmG + EGRID) {
        int pb = blockIdx.x - gemmG - EGRID;
        int base = pb * 64;
        int lim = min(64, nA - base);
        if (tid < 64 && tid < lim) {
            int v = g_list[lin][base + tid];
            rid[tid] = v;
            sth[tid] = tanhf(g_score[v]);
        }
        __syncthreads();
        int c = tid & 127, half = tid >> 7;
        int j0 = half * 32, j1 = min(lim, j0 + 32);
        float msum = 0.f, mmax = __int_as_float(0xff800000);
        for (int j = j0; j < j1; j++) {
            float val = __half2float(g_hrelu[rid[j] * 128 + c]) * sth[j];
            msum += val;
            mmax = fmaxf(mmax, val);
        }
        if (j0 < lim) {
            atomicAdd(&g_mean[c], msum * invk);
            atomicMaxF(&g_bmax[poolBm * 128 + c], mmax);
        }
        return;
    }
    if (blockIdx.x >= gemmG) {
        int i = (blockIdx.x - gemmG) * 256 + tid;
        if (i >= EE) return;
        int s = src[i], d = dst[i];
        if (mode == 0) {
            atomicAdd(&g_deg_out[s], 1);
            g_ord[i] = atomicAdd(&g_deg_in[d], 1);
        } else if (g_alive[s] && g_alive[d]) {
            atomicAdd(&g_deg_out[s], 1);
            atomicAdd(&g_deg_in[d], 1);
        }
        return;
    }
    // gemm role (HMMA)
    if (tid < 64) {
        int r = blockIdx.x * 64 + tid;
        int v = (r < nA) ? g_list[lin][r] : -1;
        rid[tid] = v;
        sth[tid] = (v >= 0) ? (useTh ? tanhf(g_score[v]) : 1.0f) : 0.f;
    }
    __syncthreads();
    for (int i = tid; i < 2048; i += 256) {
        int row = i >> 5, c4 = (i & 31) * 4;
        int v = rid[row];
        __half2 h01, h23;
        if (v >= 0) {
            if (x) {
                float4 xv = *(const float4*)&x[v * 128 + c4];
                h01 = __floats2half2_rn(xv.x, xv.y);
                h23 = __floats2half2_rn(xv.z, xv.w);
            } else {
                uint2 p = *(const uint2*)&g_hrelu[v * 128 + c4];
                h01 = *(__half2*)&p.x;
                h23 = *(__half2*)&p.y;
            }
        } else {
            h01 = __floats2half2_rn(0.f, 0.f);
            h23 = h01;
        }
        *(__half2*)&XSH[row * 136 + c4] = h01;
        *(__half2*)&XSH[row * 136 + c4 + 2] = h23;
    }
    __syncthreads();
    int w = tid >> 5;
    int rr = (w & 3) * 16, ch = (w >> 2) * 64;
    wmma::fragment<wmma::matrix_a, 16, 16, 16, __half, wmma::row_major> fa;
    wmma::fragment<wmma::matrix_b, 16, 16, 16, __half, wmma::row_major> fb;
    wmma::fragment<wmma::accumulator, 16, 16, 16, float> fc[4];
#pragma unroll
    for (int f = 0; f < 4; f++) wmma::fill_fragment(fc[f], 0.f);
    const __half* Wh = g_Wh + mode * 16384;
#pragma unroll
    for (int k0 = 0; k0 < 128; k0 += 16) {
        wmma::load_matrix_sync(fa, XSH + rr * 136 + k0, 136);
#pragma unroll
        for (int f = 0; f < 4; f++) {
            wmma::load_matrix_sync(fb, Wh + k0 * 128 + ch + f * 16, 128);
            wmma::mma_sync(fc[f], fa, fb, fc[f]);
        }
    }
    __syncthreads();
#pragma unroll
    for (int f = 0; f < 4; f++)
        wmma::store_matrix_sync(OUT + rr * 128 + ch + f * 16, fc[f], 128, wmma::mem_row_major);
    __syncthreads();
    for (int i = tid; i < 2048; i += 256) {
        int row = i >> 5, c4 = (i & 31) * 4;
        int v = rid[row];
        if (v >= 0) {
            float s = sth[row];
            float4 o = *(float4*)&OUT[row * 128 + c4];
            __half2 h01 = __floats2half2_rn(o.x * s, o.y * s);
            __half2 h23 = __floats2half2_rn(o.z * s, o.w * s);
            uint2 st;
            st.x = *(unsigned*)&h01; st.y = *(unsigned*)&h23;
            *(uint2*)&g_hs[v * 128 + c4] = st;
        }
    }
}
// b0 only: rowptr exclusive scan + frozen degree copy (196 blocks, parallel)
__global__ void k_alloc() {
    int i = blockIdx.x * blockDim.x + threadIdx.x;
    int lane = threadIdx.x & 31;
    int d = (i < NN) ? g_deg_in[i] : 0;
    int x = d;
#pragma unroll
    for (int o = 1; o < 32; o <<= 1) { int t = __shfl_up_sync(~0u, x, o); if (lane >= o) x += t; }
    int base;
    if (lane == 31) base = atomicAdd(&g_total, x);
    base = __shfl_sync(~0u, base, 31);
    if (i < NN) { g_rowptr[i] = base + x - d; g_deg0[i] = d; }
}
__global__ void k_scatter(const int* __restrict__ src, const int* __restrict__ dst) {
    int i = blockIdx.x * blockDim.x + threadIdx.x;
    if (i >= EE) return;
    g_csr[g_rowptr[dst[i]] + g_ord[i]] = src[i];
}
// gather-SpMM; HFMA2 half2 accumulation, fp32 conversion once per node.
// Dead u flagged deg_out = -1 -> ns half2 bits are 0 -> skipped by int test.
__global__ __launch_bounds__(256) void k_spmm_conv(const float* __restrict__ cb,
                                                   const float* __restrict__ sW,
                                                   int lin, int nA) {
    int gw = (blockIdx.x * blockDim.x + threadIdx.x) >> 5;
    int lane = threadIdx.x & 31;
    if (gw >= nA) return;
    int v = g_list[lin][gw];
    int s = g_rowptr[v];
    int nb = g_deg0[v];
    __half2 acc01 = __floats2half2_rn(0.f, 0.f);
    __half2 acc23 = acc01;
    for (int i0 = 0; i0 < nb; i0 += 32) {
        int u32 = 0; int nsb = 0;
        if (i0 + lane < nb) {
            u32 = g_csr[s + i0 + lane];
            int du = g_deg_out[u32];
            float nsf = (du < 0) ? 0.f : invs(du);
            __half2 nh = __float2half2_rn(nsf);
            nsb = *(int*)&nh;
        }
        int lim = min(32, nb - i0);
        for (int j = 0; j < lim; j++) {
            int nb_ = __shfl_sync(~0u, nsb, j);
            int u = __shfl_sync(~0u, u32, j);
            if (nb_ != 0) {
                uint2 p = *(const uint2*)&g_hs[u * 128 + lane * 4];
                __half2 nh = *(__half2*)&nb_;
                acc01 = __hfma2(*(__half2*)&p.x, nh, acc01);
                acc23 = __hfma2(*(__half2*)&p.y, nh, acc23);
            }
        }
    }
    float2 a01 = __half22float2(acc01);
    float2 a23 = __half22float2(acc23);
    float ndv = invs(g_deg_in[v]);
    float4 b = *(const float4*)&cb[lane * 4];
    float4 hr;
    hr.x = fmaxf(fmaf(a01.x, ndv, b.x), 0.f);
    hr.y = fmaxf(fmaf(a01.y, ndv, b.y), 0.f);
    hr.z = fmaxf(fmaf(a23.x, ndv, b.z), 0.f);
    hr.w = fmaxf(fmaf(a23.y, ndv, b.w), 0.f);
    __half2 h01 = __floats2half2_rn(hr.x, hr.y);
    __half2 h23 = __floats2half2_rn(hr.z, hr.w);
    uint2 o;
    o.x = *(unsigned*)&h01; o.y = *(unsigned*)&h23;
    *(uint2*)&g_hrelu[v * 128 + lane * 4] = o;
    float4 w = *(const float4*)&sW[lane * 4];
    float sd = hr.x * w.x + hr.y * w.y + hr.z * w.z + hr.w * w.w;
#pragma unroll
    for (int oo = 16; oo; oo >>= 1) sd += __shfl_down_sync(~0u, sd, oo);
    if (lane == 0) g_hs2[v] = sd * invs(g_deg_out[v]);
}
// score + key + hist; LAST block picks the k-th-largest 16-bit bucket
__global__ __launch_bounds__(256) void k_spmm_score(const float* __restrict__ sb,
                                                    int lin, int nA, int k) {
    __shared__ bool isLast;
    __shared__ int A[256];
    int tid = threadIdx.x;
    int gw = (blockIdx.x * 256 + tid) >> 5;
    int lane = tid & 31;
    if (gw < nA) {
        int v = g_list[lin][gw];
        int s = g_rowptr[v], e = s + g_deg0[v];
        float sum = 0.f;
        for (int i = s + lane; i < e; i += 32) sum += g_hs2[g_csr[i]];
#pragma unroll
        for (int o = 16; o; o >>= 1) sum += __shfl_down_sync(~0u, sum, o);
        if (lane == 0) {
            float sc = fmaf(sum, invs(g_deg_in[v]), sb[0]);
            g_score[v] = sc;
            unsigned kk = okey(sc);
            g_key[v] = kk;
            atomicAdd(&g_hist[kk >> 16], 1);
        }
    }
    __threadfence();
    __syncthreads();
    if (tid == 0) isLast = (atomicAdd(&g_done, 1) == gridDim.x - 1);
    __syncthreads();
    if (!isLast) return;
    if (tid == 0) g_done = 0;
    const int4* h4 = (const int4*)g_hist;
    int base4 = tid * 64;
    int s = 0;
#pragma unroll 8
    for (int b = 0; b < 64; b++) { int4 v = h4[base4 + b]; s += v.x + v.y + v.z + v.w; }
    A[tid] = s;
    __syncthreads();
    for (int off = 1; off < 256; off <<= 1) {
        int w = A[tid] + ((tid + off < 256) ? A[tid + off] : 0);
        __syncthreads();
        A[tid] = w;
        __syncthreads();
    }
    int above = A[tid] - s;
    if (above < k && above + s >= k) {
        int cum = above;
        int base = tid * 256;
        for (int b = 255; b >= 0; b--) {
            int h = g_hist[base + b];
            if (cum + h >= k) { g_bucketHi = base + b; g_cntAbove = cum; break; }
            cum += h;
        }
    }
}
// split + kill + hist zero; LAST block refines low 16 bits
__global__ __launch_bounds__(256) void k_cand(int lin, int lout, int nA, int k) {
    __shared__ bool isLast;
    __shared__ int hist[256];
    __shared__ int sh_b1, sh_rem1, sh_b0, sh_needed, sh_tc;
    __shared__ int tiebuf[TCAP];
    int tid = threadIdx.x;
    int gid = blockIdx.x * 256 + tid;
    for (int j = gid; j < HB; j += gridDim.x * 256) g_hist[j] = 0;
    int bh = g_bucketHi;
    int v = -1; unsigned key = 0; int hi = -1;
    if (gid < nA) { v = g_list[lin][gid]; key = g_key[v]; hi = (int)(key >> 16); }
    bool gt = (gid < nA) && (hi > bh);
    bool eq = (gid < nA) && (hi == bh);
    int lane = tid & 31;
    unsigned m = __ballot_sync(~0u, gt);
    if (m) {
        int ldr = __ffs(m) - 1; int base;
        if (lane == ldr) base = atomicAdd(&g_selcnt, __popc(m));
        base = __shfl_sync(~0u, base, ldr);
        if (gt) {
            g_list[lout][base + __popc(m & ((1u << lane) - 1))] = v;
            g_deg_in[v] = 0; g_deg_out[v] = 0;
        }
    }
    unsigned m2 = __ballot_sync(~0u, eq);
    if (m2) {
        int ldr = __ffs(m2) - 1; int base;
        if (lane == ldr) base = atomicAdd(&g_candcnt, __popc(m2));
        base = __shfl_sync(~0u, base, ldr);
        if (eq) {
            int p = base + __popc(m2 & ((1u << lane) - 1));
            g_candk[p] = key; g_candv[p] = v;
        }
    }
    if (gid < nA && !gt && !eq) { g_alive[v] = 0; g_deg_out[v] = -1; g_hs2[v] = 0.f; }
    __threadfence();
    __syncthreads();
    if (tid == 0) isLast = (atomicAdd(&g_done, 1) == gridDim.x - 1);
    __syncthreads();
    if (!isLast) return;
    if (tid == 0) g_done = 0;
    int C = g_candcnt;
    int kp = k - g_cntAbove;
    hist[tid] = 0;
    if (tid == 0) sh_tc = 0;
    __syncthreads();
    for (int i = tid; i < C; i += 256) atomicAdd(&hist[(g_candk[i] >> 8) & 255], 1);
    __syncthreads();
    if (tid == 0) {
        int cum = 0;
        for (int b = 255; b >= 0; b--) {
            int h = hist[b];
            if (cum + h >= kp) { sh_b1 = b; sh_rem1 = kp - cum; break; }
            cum += h;
        }
    }
    __syncthreads();
    int b1 = sh_b1, rem1 = sh_rem1;
    hist[tid] = 0;
    __syncthreads();
    for (int i = tid; i < C; i += 256) {
        unsigned kk = g_candk[i];
        if ((int)((kk >> 8) & 255) == b1) atomicAdd(&hist[kk & 255], 1);
    }
    __syncthreads();
    if (tid == 0) {
        int cum = 0;
        for (int b = 255; b >= 0; b--) {
            int h = hist[b];
            if (cum + h >= rem1) { sh_b0 = b; sh_needed = rem1 - cum; break; }
            cum += h;
        }
    }
    __syncthreads();
    unsigned lo_t = ((unsigned)b1 << 8) | (unsigned)sh_b0;
    int needed = sh_needed;
    for (int i = tid; i < C; i += 256) {
        unsigned lo = g_candk[i] & 0xFFFFu;
        int vv = g_candv[i];
        if (lo > lo_t) {
            int p = atomicAdd(&g_selcnt, 1);
            g_list[lout][p] = vv;
            g_deg_in[vv] = 0; g_deg_out[vv] = 0;
        } else if (lo < lo_t) {
            g_alive[vv] = 0; g_deg_out[vv] = -1; g_hs2[vv] = 0.f;
        } else {
            int p = atomicAdd(&sh_tc, 1);
            if (p < TCAP) tiebuf[p] = vv;
        }
    }
    __syncthreads();
    int T = sh_tc;
    if (T <= needed) {
        for (int i = tid; i < C; i += 256) {
            if ((g_candk[i] & 0xFFFFu) == lo_t) {
                int vv = g_candv[i];
                int p = atomicAdd(&g_selcnt, 1);
                g_list[lout][p] = vv;
                g_deg_in[vv] = 0; g_deg_out[vv] = 0;
            }
        }
    } else if (T <= TCAP) {
        for (int j = tid; j < T; j += 256) {
            int vj = tiebuf[j];
            int r = 0;
            for (int q = 0; q < T; q++) r += (tiebuf[q] < vj);
            if (r < needed) {
                int p = atomicAdd(&g_selcnt, 1);
                g_list[lout][p] = vj;
                g_deg_in[vj] = 0; g_deg_out[vj] = 0;
            } else { g_alive[vj] = 0; g_deg_out[vj] = -1; g_hs2[vj] = 0.f; }
        }
    } else {
        for (int i = tid; i < C; i += 256) {
            if ((g_candk[i] & 0xFFFFu) != lo_t) continue;
            int vi = g_candv[i];
            int r = 0;
            for (int q = 0; q < C; q++)
                if ((g_candk[q] & 0xFFFFu) == lo_t && g_candv[q] < vi) r++;
            if (r < needed) {
                int p = atomicAdd(&g_selcnt, 1);
                g_list[lout][p] = vi;
                g_deg_in[vi] = 0; g_deg_out[vi] = 0;
            } else { g_alive[vi] = 0; g_deg_out[vi] = -1; g_hs2[vi] = 0.f; }
        }
    }
    __syncthreads();
    if (tid == 0) { g_selcnt = 0; g_candcnt = 0; g_total = 0; }
}
__global__ __launch_bounds__(128) void k_pool(int bm, int lst, int kb, float invk) {
    __shared__ float sth[64];
    __shared__ int sv[64];
    int c = threadIdx.x;
    int base = blockIdx.x * 64;
    int lim = min(64, kb - base);
    if (c < 64 && c < lim) {
        int v = g_list[lst][base + c];
        sv[c] = v;
        sth[c] = tanhf(g_score[v]);
    }
    __syncthreads();
    float msum = 0.f, mmax = __int_as_float(0xff800000);
    for (int j = 0; j < lim; j++) {
        float val = __half2float(g_hrelu[sv[j] * 128 + c]) * sth[j];
        msum += val;
        mmax = fmaxf(mmax, val);
    }
    atomicAdd(&g_mean[c], msum * invk);
    atomicMaxF(&g_bmax[bm * 128 + c], mmax);
}
__global__ __launch_bounds__(1024) void k_mlp(const float* __restrict__ seq,
                                              const float* __restrict__ W1, const float* __restrict__ b1,
                                              const float* __restrict__ W2, const float* __restrict__ b2,
                                              const float* __restrict__ W3, const float* __restrict__ b3,
                                              float* __restrict__ out) {
    __shared__ float fin[1280];
    __shared__ float red[1024];
    __shared__ float f1[256];
    __shared__ float f2[128];
    int t = threadIdx.x;
    for (int i = t; i < 1280; i += 1024) {
        float v;
        if (i < 128)      v = g_mean[i];
        else if (i < 256) v = g_bmax[i - 128] + g_bmax[128 + (i - 128)] + g_bmax[256 + (i - 128)];
        else              v = seq[i - 256];
        fin[i] = v;
    }
    __syncthreads();
    {
        int o = t & 255, part = t >> 8;
        float acc = 0.f;
        int k0 = part * 320;
        for (int k = k0; k < k0 + 320; k++) acc = fmaf(fin[k], W1[k * 256 + o], acc);
        red[t] = acc;
    }
    __syncthreads();
    if (t < 256) {
        float s = red[t] + red[t + 256] + red[t + 512] + red[t + 768] + b1[t];
        f1[t] = fmaxf(s, 0.f);
    }
    __syncthreads();
    if (t < 128) {
        float acc = b2[t];
        for (int k = 0; k < 256; k++) acc = fmaf(f1[k], W2[k * 128 + t], acc);
        f2[t] = fmaxf(acc, 0.f);
    }
    __syncthreads();
#pragma unroll
    for (int r = 0; r < 2; r++) {
        int o = t + r * 1024;
        float acc = b3[o];
        for (int k = 0; k < 128; k++) acc = fmaf(f2[k], W3[k * 2048 + o], acc);
        out[o] = acc;
    }
}

extern "C" void kernel_launch(void* const* d_in, const int* in_sizes, int n_in,
                              void* d_out, int out_size) {
    const float* feat = (const float*)d_in[0];
    const float* seq  = (const float*)d_in[1];
    const int*   src  = (const int*)d_in[2];
    const int*   dst  = (const int*)d_in[3];
    const float* cW[3] = {(const float*)d_in[6],  (const float*)d_in[10], (const float*)d_in[14]};
    const float* cb[3] = {(const float*)d_in[7],  (const float*)d_in[11], (const float*)d_in[15]};
    const float* sW[3] = {(const float*)d_in[8],  (const float*)d_in[12], (const float*)d_in[16]};
    const float* sb[3] = {(const float*)d_in[9],  (const float*)d_in[13], (const float*)d_in[17]};
    const float* l1W = (const float*)d_in[18];
    const float* l1b = (const float*)d_in[19];
    const float* l2W = (const float*)d_in[20];
    const float* l2b = (const float*)d_in[21];
    const float* l3W = (const float*)d_in[22];
    const float* l3b = (const float*)d_in[23];
    float* out = (float*)d_out;

    const int nAv[3] = {50000, 25000, 12500};
    const int kbv[3] = {25000, 12500, 6250};

    k_init0<<<(HB + 255) / 256, 256>>>(cW[0], cW[1], cW[2]);
    for (int b = 0; b < 3; b++) {
        int nA = nAv[b], kb = kbv[b];
        int lin = b & 1, lout = 1 - lin;
        int gemmG = (nA + 63) / 64;
        int poolG = (b > 0) ? gemmG : 0;
        k_front<<<gemmG + EGRID + poolG, 256>>>(
            b == 0 ? feat : (const float*)0, lin, nA, b > 0,
            src, dst, b, gemmG, b - 1, 1.0f / (float)nA);
        if (b == 0) {
            k_alloc<<<(NN + 255) / 256, 256>>>();
            k_scatter<<<EGRID, 256>>>(src, dst);
        }
        k_spmm_conv<<<(nA + 7) / 8, 256>>>(cb[b], sW[b], lin, nA);
        k_spmm_score<<<(nA + 7) / 8, 256>>>(sb[b], lin, nA, kb);
        k_cand<<<(nA + 255) / 256, 256>>>(lin, lout, nA, kb);
    }
    k_pool<<<(6250 + 63) / 64, 128>>>(2, 1, 6250, 1.0f / 6250.0f);
    k_mlp<<<1, 1024>>>(seq, l1W, l1b, l2W, l2b, l3W, l3b, out);
}